// round 11
// baseline (speedup 1.0000x reference)
#include <cuda_runtime.h>
#include <math.h>

#define BB 32
#define NV 512
#define NODE_F 64
#define EDGE_F 16
#define MSG 80
#define OUT3 128
#define TGT 16

#define CHUNK 32        // output nodes per block
#define HLO 44          // h rows held: CHUNK + 12 halo
#define LNODES 40       // nodes updated per block: CHUNK + 8
#define NCHUNK 16       // NV / CHUNK
#define NBLOCKS (NCHUNK * BB)   // 512

// smem layout (floats)
#define OFF_HA    0
#define OFF_HB    (OFF_HA + HLO*NODE_F)          // 2816
#define OFF_ME    (OFF_HB + HLO*NODE_F)          // 5632
#define OFF_G4    (OFF_ME + LNODES*EDGE_F)       // 6272
#define OFF_INT   (OFF_G4 + LNODES*4)            // 6432 (176 ints)
#define OFF_MS    (OFF_INT + 176)                // 6608 (16B aligned: 6608*4%16==0)
#define OFF_RED   (OFF_MS + 4*4*MSG)             // 7888
#define OFF_SUM   (OFF_RED + 64)                 // 7952
#define SMEM_FLOATS (OFF_SUM + 64)               // 8016 -> 32064 B

#define FMA2(acc, a, b) asm("fma.rn.f32x2 %0, %1, %2, %0;" : "+l"(acc) : "l"(a), "l"(b))
__device__ __forceinline__ float2 unpack2(unsigned long long v) {
    float2 r; asm("mov.b64 {%0,%1}, %2;" : "=f"(r.x), "=f"(r.y) : "l"(v)); return r;
}
#define NBAR(id) asm volatile("bar.sync %0, %1;" :: "r"(id), "r"(128) : "memory")

// ---------------- device globals ----------------
__device__ float d_acc[BB * OUT3];   // zero at load; re-zeroed by epilogue
__device__ int   d_done = 0;
// quad-major H: u64[ ((step*4+bkt)*20 + i4)*64 + c ][2]
__device__ __align__(16) float d_Ht4[3 * 4 * 20 * NODE_F * 4];
__device__ __align__(16) float d_Wt2[4 * 32 * OUT3 * 2];  // [layer][i2][col] float2

// ---------------------------------------------------------------------------
// transpose H (quad-major) and W (pair-major)
// ---------------------------------------------------------------------------
#define HJOBS (3*4*20*NODE_F*2)      // 30720 float2 jobs
#define WJOBS (4*32*OUT3)            // 16384
__global__ void transpose_kernel(const float* __restrict__ H0,
                                 const float* __restrict__ H1,
                                 const float* __restrict__ H2,
                                 const float* __restrict__ W0,
                                 const float* __restrict__ W1,
                                 const float* __restrict__ W2,
                                 const float* __restrict__ W3) {
    int idx = blockIdx.x * 256 + threadIdx.x;
    if (idx < HJOBS) {
        int s  = idx / 10240;
        int r  = idx - s * 10240;
        int d  = r / 2560;
        int r2 = r - d * 2560;
        int i4 = r2 / 128;
        int r3 = r2 - i4 * 128;
        int c  = r3 >> 1;
        int half = r3 & 1;
        int row = 4 * i4 + 2 * half;
        const float* H = (s == 0) ? H0 : (s == 1) ? H1 : H2;
        reinterpret_cast<float2*>(d_Ht4)[idx] =
            make_float2(H[(d * MSG + row) * NODE_F + c],
                        H[(d * MSG + row + 1) * NODE_F + c]);
    } else if (idx < HJOBS + WJOBS) {
        int j = idx - HJOBS;
        int layer = j / (32 * OUT3);
        int r = j - layer * (32 * OUT3);
        int i2 = r / OUT3;
        int col = r - i2 * OUT3;
        const float* W = (layer == 0) ? W0 : (layer == 1) ? W1 : (layer == 2) ? W2 : W3;
        reinterpret_cast<float2*>(d_Wt2)[j] =
            make_float2(W[(2 * i2) * OUT3 + col], W[(2 * i2 + 1) * OUT3 + col]);
    }
}

// ---------------------------------------------------------------------------
// one message step (4 warps): hnext[l] = [gather(hprev)|me] @ H[bucket]
// ---------------------------------------------------------------------------
__device__ __forceinline__ void do_step(
    const float* __restrict__ hprev, float* __restrict__ hnext,
    const ulonglong2* __restrict__ Hstep,
    const int* __restrict__ list_s, const int* __restrict__ bucket_s,
    const float* __restrict__ g4f, const float* __restrict__ me_s,
    float* __restrict__ m_s, int G, int w, int lane)
{
    float* mw = m_s + w * (4 * MSG);
    for (int gi = w; gi < G; gi += 4) {
        int l4[4];
#pragma unroll
        for (int j = 0; j < 4; j++) {
            int l = list_s[4 * gi + j];
            l4[j] = l;
            float4 gg = *reinterpret_cast<const float4*>(g4f + l * 4);
            const float* hp = hprev + (l + 1) * NODE_F + 2 * lane;
            float2 h0 = *reinterpret_cast<const float2*>(hp);
            float2 h1 = *reinterpret_cast<const float2*>(hp + NODE_F);
            float2 h2 = *reinterpret_cast<const float2*>(hp + 2 * NODE_F);
            float2 h3 = *reinterpret_cast<const float2*>(hp + 3 * NODE_F);
            float2 m2;
            m2.x = gg.x * h0.x + gg.y * h1.x + gg.z * h2.x + gg.w * h3.x;
            m2.y = gg.x * h0.y + gg.y * h1.y + gg.z * h2.y + gg.w * h3.y;
            *reinterpret_cast<float2*>(mw + j * MSG + 2 * lane) = m2;
            if (lane < 16) mw[j * MSG + 64 + lane] = me_s[l * EDGE_F + lane];
        }
        __syncwarp();
        int bucket = bucket_s[l4[0]];
        const ulonglong2* Hb = Hstep + bucket * (20 * NODE_F);
        unsigned long long a0[4], a1[4];
#pragma unroll
        for (int j = 0; j < 4; j++) { a0[j] = 0ull; a1[j] = 0ull; }
#pragma unroll 4
        for (int i4 = 0; i4 < 20; i4++) {
            ulonglong2 ha  = __ldg(Hb + i4 * NODE_F + lane);
            ulonglong2 hb2 = __ldg(Hb + i4 * NODE_F + lane + 32);
#pragma unroll
            for (int j = 0; j < 4; j++) {
                ulonglong2 mm =
                    *reinterpret_cast<const ulonglong2*>(mw + j * MSG + 4 * i4);
                FMA2(a0[j], mm.x, ha.x);
                FMA2(a0[j], mm.y, ha.y);
                FMA2(a1[j], mm.x, hb2.x);
                FMA2(a1[j], mm.y, hb2.y);
            }
        }
#pragma unroll
        for (int j = 0; j < 4; j++) {
            float2 r0 = unpack2(a0[j]);
            float2 r1 = unpack2(a1[j]);
            float* dst = hnext + l4[j] * NODE_F;
            dst[lane] = r0.x + r0.y;
            dst[lane + 32] = r1.x + r1.y;
        }
        __syncwarp();
    }
}

// ---------------------------------------------------------------------------
// readout by a 128-thread group: nodes [nbase, nbase+8*nbatch); thread owns
// one output column. shfl-tree reductions; mask from bucket validity.
// ---------------------------------------------------------------------------
__device__ __forceinline__ float do_readout(
    const float* __restrict__ hbuf, const unsigned long long* __restrict__ Wt,
    int nbase, int nbatch,
    float* __restrict__ red, float* __restrict__ sum,
    const int* __restrict__ bucket_s, int use_mask,
    int col, int lw, int lane, int barid)
{
    unsigned long long Wr2[32];
#pragma unroll
    for (int i = 0; i < 32; i++) Wr2[i] = __ldg(Wt + i * OUT3 + col);

    const ulonglong2* h2 = reinterpret_cast<const ulonglong2*>(hbuf);
    float accLoc = 0.f;

    for (int batch = 0; batch < nbatch; batch++) {
        int nb = nbase + batch * 8;
        unsigned long long aA[8];
#pragma unroll
        for (int j = 0; j < 8; j++) aA[j] = 0ull;
#pragma unroll
        for (int i4 = 0; i4 < 16; i4++) {
#pragma unroll
            for (int j = 0; j < 8; j++) {
                ulonglong2 hv = h2[(nb + j) * 16 + i4];
                FMA2(aA[j], hv.x, Wr2[2 * i4]);
                FMA2(aA[j], hv.y, Wr2[2 * i4 + 1]);
            }
        }
        float lin[8];
#pragma unroll
        for (int j = 0; j < 8; j++) {
            float2 p = unpack2(aA[j]);
            lin[j] = p.x + p.y;
        }
#pragma unroll
        for (int j = 0; j < 8; j++) {
            float m = lin[j];
#pragma unroll
            for (int k = 16; k >= 1; k >>= 1) m = fmaxf(m, __shfl_xor_sync(0xffffffffu, m, k));
            if (lane == 0) red[lw * 8 + j] = m;
        }
        NBAR(barid);
        float ev[8];
#pragma unroll
        for (int j = 0; j < 8; j++) {
            float gm = fmaxf(fmaxf(red[0 * 8 + j], red[1 * 8 + j]),
                             fmaxf(red[2 * 8 + j], red[3 * 8 + j]));
            ev[j] = __expf(lin[j] - gm);
        }
#pragma unroll
        for (int j = 0; j < 8; j++) {
            float s = ev[j];
#pragma unroll
            for (int k = 16; k >= 1; k >>= 1) s += __shfl_xor_sync(0xffffffffu, s, k);
            if (lane == 0) sum[lw * 8 + j] = s;
        }
        NBAR(barid);
#pragma unroll
        for (int j = 0; j < 8; j++) {
            float gs = sum[0 * 8 + j] + sum[1 * 8 + j] + sum[2 * 8 + j] + sum[3 * 8 + j];
            int keep = use_mask ? (bucket_s[nb + j] >= 0) : 1;
            if (keep) accLoc += __fdividef(ev[j], gs);
        }
    }
    return accLoc;
}

// ---------------------------------------------------------------------------
// mega kernel: one 32-node chunk per block; 3 steps + 4 readouts fused.
// Group A (warps 0-3): steps. Group B (warps 4-7): readouts (4 batches/layer).
// Layer-3 readout splits 2/2. Last block runs the final GEMM+softmax epilogue.
// grid (16, 32) x 256; 3 blocks/SM.
// ---------------------------------------------------------------------------
__global__ void __launch_bounds__(256, 3) mega_kernel(
    const float* __restrict__ g, const float* __restrict__ h_in,
    const float* __restrict__ e,
    const float* __restrict__ Wf, const float* __restrict__ bf,
    float* __restrict__ out)
{
    extern __shared__ float sm[];
    float* hA   = sm + OFF_HA;
    float* hB   = sm + OFF_HB;
    float* me_s = sm + OFF_ME;
    float* g4f  = sm + OFF_G4;
    int*   ip   = (int*)(sm + OFF_INT);
    int* bucket_s = ip;            // 40
    int* list_s   = ip + 72;       // up to 56
    int* bcnt     = ip + 160;      // 4
    int* boff     = ip + 164;      // 4
    int* pcnt     = ip + 168;      // 4
    int* gtot     = ip + 172;
    int* vflag    = ip + 173;
    int* lastf    = ip + 174;
    float* m_s  = sm + OFF_MS;
    float* redA = sm + OFF_RED;        float* redB = sm + OFF_RED + 32;
    float* sumA = sm + OFF_SUM;        float* sumB = sm + OFF_SUM + 32;

    int tid = threadIdx.x;
    int b = blockIdx.y;
    int s = blockIdx.x * CHUNK;
    int w = tid >> 5, lane = tid & 31;
    int col = tid & 127;
    int lw = (tid >> 5) & 3;

    if (tid < 4) { bcnt[tid] = 0; pcnt[tid] = 0; }

    // load h0 rows [s, s+HLO) (wrapped) into hA
    for (int i = tid; i < HLO * 16; i += 256) {
        int row = i >> 4, q = i & 15;
        int v = (s + row) & (NV - 1);
        reinterpret_cast<float4*>(hA)[i] =
            __ldg(reinterpret_cast<const float4*>(h_in + ((size_t)(b * NV + v) << 6)) + q);
    }
    // g4 + degree bucket
    if (tid < LNODES) {
        int v = (s + tid) & (NV - 1);
        const float* grow = g + (size_t)(b * NV + v) * NV;
        float g0 = __ldg(grow + ((v + 1) & (NV - 1)));
        float g1 = __ldg(grow + ((v + 2) & (NV - 1)));
        float g2 = __ldg(grow + ((v + 3) & (NV - 1)));
        float g3 = __ldg(grow + ((v + 4) & (NV - 1)));
        g4f[tid * 4 + 0] = g0; g4f[tid * 4 + 1] = g1;
        g4f[tid * 4 + 2] = g2; g4f[tid * 4 + 3] = g3;
        float deg = g0 + g1 + g2 + g3;
        int d = (int)(deg + 0.5f) - 1;
        bool valid = (d >= 0) && (d < 4) && (fabsf(deg - (float)(d + 1)) < 1e-4f);
        if (valid) { atomicAdd(&bcnt[d], 1); bucket_s[tid] = d; }
        else bucket_s[tid] = -1;
    }
    __syncthreads();
    if (tid == 0) {
        int off = 0, gt = 0, tot = 0;
        for (int d = 0; d < 4; d++) {
            boff[d] = off;
            int pc = (bcnt[d] + 3) & ~3;
            off += pc; gt += pc >> 2; tot += bcnt[d];
        }
        gtot[0] = gt;
        vflag[0] = (tot == LNODES);
    }
    __syncthreads();
    if (tid < LNODES && bucket_s[tid] >= 0) {
        int d = bucket_s[tid];
        int pos = atomicAdd(&pcnt[d], 1);
        list_s[boff[d] + pos] = tid;
    }
    // me = banded edge message
    for (int i = tid; i < LNODES * EDGE_F; i += 256) {
        int l = i >> 4, c = i & 15;
        int v = (s + l) & (NV - 1);
        const float* eb = e + ((size_t)(b * NV + v) * NV) * EDGE_F;
        me_s[i] = g4f[l * 4 + 0] * __ldg(eb + ((v + 1) & (NV - 1)) * EDGE_F + c)
                + g4f[l * 4 + 1] * __ldg(eb + ((v + 2) & (NV - 1)) * EDGE_F + c)
                + g4f[l * 4 + 2] * __ldg(eb + ((v + 3) & (NV - 1)) * EDGE_F + c)
                + g4f[l * 4 + 3] * __ldg(eb + ((v + 4) & (NV - 1)) * EDGE_F + c);
    }
    __syncthreads();
    if (tid < 4) {   // pad bucket lists to multiple of 4
        int c = bcnt[tid];
        if (c > 0) {
            int pc = (c + 3) & ~3;
            int last = list_s[boff[tid] + c - 1];
            for (int p = c; p < pc; p++) list_s[boff[tid] + p] = last;
        }
    }
    __syncthreads();
    int G = gtot[0];
    int allvalid = vflag[0];
    int msk = !allvalid;

    const ulonglong2* Ht4 = reinterpret_cast<const ulonglong2*>(d_Ht4);
    const unsigned long long* Wt = reinterpret_cast<const unsigned long long*>(d_Wt2);
    const int HSTEP = 4 * 20 * NODE_F;   // ulonglong2 per step
    const int WSTEP = 32 * OUT3;         // u64 per layer

    float accA = 0.f, accB = 0.f;

    // phase 1: A: step0 hA->hB ; B: readout(h0=hA, W0) all 4 batches
    if (w < 4) do_step(hA, hB, Ht4, list_s, bucket_s, g4f, me_s, m_s, G, w, lane);
    else       accB += do_readout(hA, Wt, 0, 4, redB, sumB, bucket_s, 0, col, lw, lane, 1);
    if (!allvalid) { __syncthreads();
        for (int i = tid; i < LNODES * NODE_F; i += 256)
            if (bucket_s[i >> 6] < 0) hB[i] = 0.f; }
    __syncthreads();

    // phase 2: A: step1 hB->hA ; B: readout(h1=hB, W1)
    if (w < 4) do_step(hB, hA, Ht4 + HSTEP, list_s, bucket_s, g4f, me_s, m_s, G, w, lane);
    else       accB += do_readout(hB, Wt + WSTEP, 0, 4, redB, sumB, bucket_s, msk, col, lw, lane, 1);
    if (!allvalid) { __syncthreads();
        for (int i = tid; i < LNODES * NODE_F; i += 256)
            if (bucket_s[i >> 6] < 0) hA[i] = 0.f; }
    __syncthreads();

    // phase 3: A: step2 hA->hB ; B: readout(h2=hA, W2)
    if (w < 4) do_step(hA, hB, Ht4 + 2 * HSTEP, list_s, bucket_s, g4f, me_s, m_s, G, w, lane);
    else       accB += do_readout(hA, Wt + 2 * WSTEP, 0, 4, redB, sumB, bucket_s, msk, col, lw, lane, 1);
    if (!allvalid) { __syncthreads();
        for (int i = tid; i < LNODES * NODE_F; i += 256)
            if (bucket_s[i >> 6] < 0) hB[i] = 0.f; }
    __syncthreads();

    // phase 4: readout(h3=hB, W3) split 2/2
    if (w < 4) accA += do_readout(hB, Wt + 3 * WSTEP, 0,  2, redA, sumA, bucket_s, msk, col, lw, lane, 2);
    else       accB += do_readout(hB, Wt + 3 * WSTEP, 16, 2, redB, sumB, bucket_s, msk, col, lw, lane, 1);

    atomicAdd(&d_acc[b * OUT3 + col], (w < 4) ? accA : accB);

    // ---- last-block epilogue: final GEMM + softmax ----
    __threadfence();
    __syncthreads();
    if (tid == 0) {
        int old = atomicAdd(&d_done, 1);
        lastf[0] = (old == NBLOCKS - 1);
    }
    __syncthreads();
    if (lastf[0]) {
        __threadfence();
        int bb = tid >> 3;          // 32 rows, 8 threads each
        int o = tid & 7;            // outputs o and o+8
        float s0 = __ldg(bf + o), s1 = __ldg(bf + o + 8);
#pragma unroll 8
        for (int i = 0; i < OUT3; i++) {
            float a = d_acc[bb * OUT3 + i];
            s0 += a * __ldg(Wf + i * TGT + o);
            s1 += a * __ldg(Wf + i * TGT + o + 8);
        }
        float m = fmaxf(s0, s1);
#pragma unroll
        for (int k = 4; k >= 1; k >>= 1) m = fmaxf(m, __shfl_xor_sync(0xffffffffu, m, k));
        float e0 = expf(s0 - m), e1 = expf(s1 - m);
        float sm2 = e0 + e1;
#pragma unroll
        for (int k = 4; k >= 1; k >>= 1) sm2 += __shfl_xor_sync(0xffffffffu, sm2, k);
        out[bb * TGT + o] = e0 / sm2;
        out[bb * TGT + o + 8] = e1 / sm2;
        // reset state for next replay
        __syncthreads();
        for (int i = tid; i < BB * OUT3; i += 256) d_acc[i] = 0.f;
        if (tid == 0) d_done = 0;
    }
}

// ---------------------------------------------------------------------------
extern "C" void kernel_launch(void* const* d_in, const int* in_sizes, int n_in,
                              void* d_out, int out_size) {
    const float* g    = (const float*)d_in[0];
    const float* h_in = (const float*)d_in[1];
    const float* e    = (const float*)d_in[2];
    const float* H0   = (const float*)d_in[3];
    const float* H1   = (const float*)d_in[4];
    const float* H2   = (const float*)d_in[5];
    const float* W0   = (const float*)d_in[6];
    const float* W1   = (const float*)d_in[7];
    const float* W2   = (const float*)d_in[8];
    const float* W3   = (const float*)d_in[9];
    const float* Wf   = (const float*)d_in[10];
    const float* bf   = (const float*)d_in[11];
    float* out = (float*)d_out;

    static int smem_set = 0;
    if (!smem_set) {
        cudaFuncSetAttribute(mega_kernel, cudaFuncAttributeMaxDynamicSharedMemorySize,
                             SMEM_FLOATS * 4);
        smem_set = 1;
    }

    transpose_kernel<<<(HJOBS + WJOBS + 255) / 256, 256>>>(H0, H1, H2, W0, W1, W2, W3);
    mega_kernel<<<dim3(NCHUNK, BB), 256, SMEM_FLOATS * 4>>>(g, h_in, e, Wf, bf, out);
}

// round 12
// speedup vs baseline: 1.6469x; 1.6469x over previous
#include <cuda_runtime.h>
#include <math.h>

#define BB 32
#define NV 512
#define NODE_F 64
#define EDGE_F 16
#define MSG 80
#define OUT3 128
#define TGT 16

#define CHUNK 64        // output nodes per block
#define HLO 76          // h rows held: CHUNK + 12 halo
#define LNODES 72       // nodes updated per block: CHUNK + 8

// smem layout (floats)
#define OFF_HA    0
#define OFF_HB    (OFF_HA + HLO*NODE_F)          // 4864
#define OFF_ME    (OFF_HB + HLO*NODE_F)          // 9728
#define OFF_G4    (OFF_ME + LNODES*EDGE_F)       // 10880
#define OFF_INT   (OFF_G4 + LNODES*4)            // 11168 (176 ints)
#define OFF_MS    (OFF_INT + 176)                // 11344 (16B aligned)
#define OFF_RED   (OFF_MS + 4*4*MSG)             // 12624
#define OFF_SUM   (OFF_RED + 64)                 // 12688
#define SMEM_FLOATS (OFF_SUM + 64)               // 12752 -> 51008 B

#define FMA2(acc, a, b) asm("fma.rn.f32x2 %0, %1, %2, %0;" : "+l"(acc) : "l"(a), "l"(b))
__device__ __forceinline__ float2 unpack2(unsigned long long v) {
    float2 r; asm("mov.b64 {%0,%1}, %2;" : "=f"(r.x), "=f"(r.y) : "l"(v)); return r;
}
#define NBAR(id) asm volatile("bar.sync %0, %1;" :: "r"(id), "r"(128) : "memory")

// ---------------- device globals ----------------
__device__ float d_acc[BB * OUT3];   // zero at load; re-zeroed by epilogue
__device__ int   d_done = 0;
// quad-major H: u64[ ((step*4+bkt)*20 + i4)*64 + c ][2]
__device__ __align__(16) float d_Ht4[3 * 4 * 20 * NODE_F * 4];
__device__ __align__(16) float d_Wt2[4 * 32 * OUT3 * 2];  // [layer][i2][col] float2

// ---------------------------------------------------------------------------
// transpose H (quad-major) and W (pair-major)
// ---------------------------------------------------------------------------
#define HJOBS (3*4*20*NODE_F*2)      // 30720 float2 jobs
#define WJOBS (4*32*OUT3)            // 16384
__global__ void transpose_kernel(const float* __restrict__ H0,
                                 const float* __restrict__ H1,
                                 const float* __restrict__ H2,
                                 const float* __restrict__ W0,
                                 const float* __restrict__ W1,
                                 const float* __restrict__ W2,
                                 const float* __restrict__ W3) {
    int idx = blockIdx.x * 256 + threadIdx.x;
    if (idx < HJOBS) {
        int s  = idx / 10240;
        int r  = idx - s * 10240;
        int d  = r / 2560;
        int r2 = r - d * 2560;
        int i4 = r2 / 128;
        int r3 = r2 - i4 * 128;
        int c  = r3 >> 1;
        int half = r3 & 1;
        int row = 4 * i4 + 2 * half;
        const float* H = (s == 0) ? H0 : (s == 1) ? H1 : H2;
        reinterpret_cast<float2*>(d_Ht4)[idx] =
            make_float2(H[(d * MSG + row) * NODE_F + c],
                        H[(d * MSG + row + 1) * NODE_F + c]);
    } else if (idx < HJOBS + WJOBS) {
        int j = idx - HJOBS;
        int layer = j / (32 * OUT3);
        int r = j - layer * (32 * OUT3);
        int i2 = r / OUT3;
        int col = r - i2 * OUT3;
        const float* W = (layer == 0) ? W0 : (layer == 1) ? W1 : (layer == 2) ? W2 : W3;
        reinterpret_cast<float2*>(d_Wt2)[j] =
            make_float2(W[(2 * i2) * OUT3 + col], W[(2 * i2 + 1) * OUT3 + col]);
    }
}

// ---------------------------------------------------------------------------
// one message step (4 warps): hnext[l] = [gather(hprev)|me] @ H[bucket]
// ---------------------------------------------------------------------------
__device__ __forceinline__ void do_step(
    const float* __restrict__ hprev, float* __restrict__ hnext,
    const ulonglong2* __restrict__ Hstep,
    const int* __restrict__ list_s, const int* __restrict__ bucket_s,
    const float* __restrict__ g4f, const float* __restrict__ me_s,
    float* __restrict__ m_s, int G, int w, int lane)
{
    float* mw = m_s + w * (4 * MSG);
    for (int gi = w; gi < G; gi += 4) {
        int l4[4];
#pragma unroll
        for (int j = 0; j < 4; j++) {
            int l = list_s[4 * gi + j];
            l4[j] = l;
            float4 gg = *reinterpret_cast<const float4*>(g4f + l * 4);
            const float* hp = hprev + (l + 1) * NODE_F + 2 * lane;
            float2 h0 = *reinterpret_cast<const float2*>(hp);
            float2 h1 = *reinterpret_cast<const float2*>(hp + NODE_F);
            float2 h2 = *reinterpret_cast<const float2*>(hp + 2 * NODE_F);
            float2 h3 = *reinterpret_cast<const float2*>(hp + 3 * NODE_F);
            float2 m2;
            m2.x = gg.x * h0.x + gg.y * h1.x + gg.z * h2.x + gg.w * h3.x;
            m2.y = gg.x * h0.y + gg.y * h1.y + gg.z * h2.y + gg.w * h3.y;
            *reinterpret_cast<float2*>(mw + j * MSG + 2 * lane) = m2;
            if (lane < 16) mw[j * MSG + 64 + lane] = me_s[l * EDGE_F + lane];
        }
        __syncwarp();
        int bucket = bucket_s[l4[0]];
        const ulonglong2* Hb = Hstep + bucket * (20 * NODE_F);
        unsigned long long a0[4], a1[4];
#pragma unroll
        for (int j = 0; j < 4; j++) { a0[j] = 0ull; a1[j] = 0ull; }
#pragma unroll 4
        for (int i4 = 0; i4 < 20; i4++) {
            ulonglong2 ha  = __ldg(Hb + i4 * NODE_F + lane);
            ulonglong2 hb2 = __ldg(Hb + i4 * NODE_F + lane + 32);
#pragma unroll
            for (int j = 0; j < 4; j++) {
                ulonglong2 mm =
                    *reinterpret_cast<const ulonglong2*>(mw + j * MSG + 4 * i4);
                FMA2(a0[j], mm.x, ha.x);
                FMA2(a0[j], mm.y, ha.y);
                FMA2(a1[j], mm.x, hb2.x);
                FMA2(a1[j], mm.y, hb2.y);
            }
        }
#pragma unroll
        for (int j = 0; j < 4; j++) {
            float2 r0 = unpack2(a0[j]);
            float2 r1 = unpack2(a1[j]);
            float* dst = hnext + l4[j] * NODE_F;
            dst[lane] = r0.x + r0.y;
            dst[lane + 32] = r1.x + r1.y;
        }
        __syncwarp();
    }
}

// ---------------------------------------------------------------------------
// readout by a 128-thread group: nodes [nbase, nbase+8*nbatch); thread owns
// one output column. shfl-tree reductions; mask from bucket validity.
// ---------------------------------------------------------------------------
__device__ __forceinline__ float do_readout(
    const float* __restrict__ hbuf, const unsigned long long* __restrict__ Wt,
    int nbase, int nbatch,
    float* __restrict__ red, float* __restrict__ sum,
    const int* __restrict__ bucket_s, int use_mask,
    int col, int lw, int lane, int barid)
{
    unsigned long long Wr2[32];
#pragma unroll
    for (int i = 0; i < 32; i++) Wr2[i] = __ldg(Wt + i * OUT3 + col);

    const ulonglong2* h2 = reinterpret_cast<const ulonglong2*>(hbuf);
    float accLoc = 0.f;

    for (int batch = 0; batch < nbatch; batch++) {
        int nb = nbase + batch * 8;
        unsigned long long aA[8];
#pragma unroll
        for (int j = 0; j < 8; j++) aA[j] = 0ull;
#pragma unroll
        for (int i4 = 0; i4 < 16; i4++) {
#pragma unroll
            for (int j = 0; j < 8; j++) {
                ulonglong2 hv = h2[(nb + j) * 16 + i4];
                FMA2(aA[j], hv.x, Wr2[2 * i4]);
                FMA2(aA[j], hv.y, Wr2[2 * i4 + 1]);
            }
        }
        float lin[8];
#pragma unroll
        for (int j = 0; j < 8; j++) {
            float2 p = unpack2(aA[j]);
            lin[j] = p.x + p.y;
        }
#pragma unroll
        for (int j = 0; j < 8; j++) {
            float m = lin[j];
#pragma unroll
            for (int k = 16; k >= 1; k >>= 1) m = fmaxf(m, __shfl_xor_sync(0xffffffffu, m, k));
            if (lane == 0) red[lw * 8 + j] = m;
        }
        NBAR(barid);
        float ev[8];
#pragma unroll
        for (int j = 0; j < 8; j++) {
            float gm = fmaxf(fmaxf(red[0 * 8 + j], red[1 * 8 + j]),
                             fmaxf(red[2 * 8 + j], red[3 * 8 + j]));
            ev[j] = __expf(lin[j] - gm);
        }
#pragma unroll
        for (int j = 0; j < 8; j++) {
            float s = ev[j];
#pragma unroll
            for (int k = 16; k >= 1; k >>= 1) s += __shfl_xor_sync(0xffffffffu, s, k);
            if (lane == 0) sum[lw * 8 + j] = s;
        }
        NBAR(barid);
#pragma unroll
        for (int j = 0; j < 8; j++) {
            float gs = sum[0 * 8 + j] + sum[1 * 8 + j] + sum[2 * 8 + j] + sum[3 * 8 + j];
            int keep = use_mask ? (bucket_s[nb + j] >= 0) : 1;
            if (keep) accLoc += __fdividef(ev[j], gs);
        }
    }
    return accLoc;
}

// ---------------------------------------------------------------------------
// mega kernel: one 64-node chunk per block; 3 steps + 4 readouts fused.
// Phase 1 hides the serial prologue: group A (warps 0-3) runs g4/bucket/me
// then step0 while group B (warps 4-7) does the full layer-0 readout (which
// needs only hA + W0). Layers 1-2: A step + 2 batches, B 6 batches.
// Layer 3: 4/4 split. Last block runs the final GEMM+softmax epilogue.
// ---------------------------------------------------------------------------
__global__ void __launch_bounds__(256, 2) mega_kernel(
    const float* __restrict__ g, const float* __restrict__ h_in,
    const float* __restrict__ e,
    const float* __restrict__ Wf, const float* __restrict__ bf,
    float* __restrict__ out)
{
    extern __shared__ float sm[];
    float* hA   = sm + OFF_HA;
    float* hB   = sm + OFF_HB;
    float* me_s = sm + OFF_ME;
    float* g4f  = sm + OFF_G4;
    int*   ip   = (int*)(sm + OFF_INT);
    int* bucket_s = ip;            // 72
    int* list_s   = ip + 72;       // 88
    int* bcnt     = ip + 160;      // 4
    int* boff     = ip + 164;      // 4
    int* pcnt     = ip + 168;      // 4
    int* gtot     = ip + 172;
    int* vflag    = ip + 173;
    int* lastf    = ip + 174;
    float* m_s  = sm + OFF_MS;
    float* redA = sm + OFF_RED;        float* redB = sm + OFF_RED + 32;
    float* sumA = sm + OFF_SUM;        float* sumB = sm + OFF_SUM + 32;

    int tid = threadIdx.x;
    int b = blockIdx.y;
    int s = blockIdx.x * CHUNK;
    int w = tid >> 5, lane = tid & 31;
    int col = tid & 127;
    int lw = (tid >> 5) & 3;

    if (tid < 4) { bcnt[tid] = 0; pcnt[tid] = 0; }

    // load h0 rows [s, s+HLO) (wrapped) into hA — all 256 threads
    for (int i = tid; i < HLO * 16; i += 256) {
        int row = i >> 4, q = i & 15;
        int v = (s + row) & (NV - 1);
        reinterpret_cast<float4*>(hA)[i] =
            __ldg(reinterpret_cast<const float4*>(h_in + ((size_t)(b * NV + v) << 6)) + q);
    }
    __syncthreads();   // hA ready; bcnt/pcnt zeroed

    const ulonglong2* Ht4 = reinterpret_cast<const ulonglong2*>(d_Ht4);
    const unsigned long long* Wt = reinterpret_cast<const unsigned long long*>(d_Wt2);
    const int HSTEP = 4 * 20 * NODE_F;   // ulonglong2 per step
    const int WSTEP = 32 * OUT3;         // u64 per layer

    float accA = 0.f, accB = 0.f;

    // ---- phase 1: A = prologue + step0 (hA->hB) ; B = full layer-0 readout
    if (w < 4) {
        // g4 + degree bucket (tids 0..71 all in group A)
        if (tid < LNODES) {
            int v = (s + tid) & (NV - 1);
            const float* grow = g + (size_t)(b * NV + v) * NV;
            float g0 = __ldg(grow + ((v + 1) & (NV - 1)));
            float g1 = __ldg(grow + ((v + 2) & (NV - 1)));
            float g2 = __ldg(grow + ((v + 3) & (NV - 1)));
            float g3 = __ldg(grow + ((v + 4) & (NV - 1)));
            g4f[tid * 4 + 0] = g0; g4f[tid * 4 + 1] = g1;
            g4f[tid * 4 + 2] = g2; g4f[tid * 4 + 3] = g3;
            float deg = g0 + g1 + g2 + g3;
            int d = (int)(deg + 0.5f) - 1;
            bool valid = (d >= 0) && (d < 4) && (fabsf(deg - (float)(d + 1)) < 1e-4f);
            if (valid) { atomicAdd(&bcnt[d], 1); bucket_s[tid] = d; }
            else bucket_s[tid] = -1;
        }
        NBAR(2);
        if (tid == 0) {
            int off = 0, gt = 0, tot = 0;
            for (int d = 0; d < 4; d++) {
                boff[d] = off;
                int pc = (bcnt[d] + 3) & ~3;
                off += pc; gt += pc >> 2; tot += bcnt[d];
            }
            gtot[0] = gt;
            vflag[0] = (tot == LNODES);
        }
        NBAR(2);
        if (tid < LNODES && bucket_s[tid] >= 0) {
            int d = bucket_s[tid];
            int pos = atomicAdd(&pcnt[d], 1);
            list_s[boff[d] + pos] = tid;
        }
        // me = banded edge message (128 threads)
        for (int i = tid; i < LNODES * EDGE_F; i += 128) {
            int l = i >> 4, c = i & 15;
            int v = (s + l) & (NV - 1);
            const float* eb = e + ((size_t)(b * NV + v) * NV) * EDGE_F;
            me_s[i] = g4f[l * 4 + 0] * __ldg(eb + ((v + 1) & (NV - 1)) * EDGE_F + c)
                    + g4f[l * 4 + 1] * __ldg(eb + ((v + 2) & (NV - 1)) * EDGE_F + c)
                    + g4f[l * 4 + 2] * __ldg(eb + ((v + 3) & (NV - 1)) * EDGE_F + c)
                    + g4f[l * 4 + 3] * __ldg(eb + ((v + 4) & (NV - 1)) * EDGE_F + c);
        }
        NBAR(2);
        if (tid < 4) {   // pad bucket lists to multiple of 4
            int c = bcnt[tid];
            if (c > 0) {
                int pc = (c + 3) & ~3;
                int last = list_s[boff[tid] + c - 1];
                for (int p = c; p < pc; p++) list_s[boff[tid] + p] = last;
            }
        }
        NBAR(2);
        do_step(hA, hB, Ht4, list_s, bucket_s, g4f, me_s, m_s, gtot[0], w, lane);
    } else {
        // layer-0 readout needs only hA + W0 (mask irrelevant for raw h0)
        accB += do_readout(hA, Wt, 0, 8, redB, sumB, bucket_s, 0, col, lw, lane, 1);
    }
    __syncthreads();   // step0 + prologue results visible to all

    int G = gtot[0];
    int allvalid = vflag[0];
    int msk = !allvalid;
    if (!allvalid) {
        for (int i = tid; i < LNODES * NODE_F; i += 256)
            if (bucket_s[i >> 6] < 0) hB[i] = 0.f;
        __syncthreads();
    }

    // ---- phase 2: A: step1 hB->hA + 2 batches h1 ; B: 6 batches h1
    if (w < 4) {
        do_step(hB, hA, Ht4 + HSTEP, list_s, bucket_s, g4f, me_s, m_s, G, w, lane);
        accA += do_readout(hB, Wt + WSTEP, 48, 2, redA, sumA, bucket_s, msk, col, lw, lane, 2);
    } else {
        accB += do_readout(hB, Wt + WSTEP, 0, 6, redB, sumB, bucket_s, msk, col, lw, lane, 1);
    }
    __syncthreads();
    if (!allvalid) {
        for (int i = tid; i < LNODES * NODE_F; i += 256)
            if (bucket_s[i >> 6] < 0) hA[i] = 0.f;
        __syncthreads();
    }

    // ---- phase 3: A: step2 hA->hB + 2 batches h2 ; B: 6 batches h2
    if (w < 4) {
        do_step(hA, hB, Ht4 + 2 * HSTEP, list_s, bucket_s, g4f, me_s, m_s, G, w, lane);
        accA += do_readout(hA, Wt + 2 * WSTEP, 48, 2, redA, sumA, bucket_s, msk, col, lw, lane, 2);
    } else {
        accB += do_readout(hA, Wt + 2 * WSTEP, 0, 6, redB, sumB, bucket_s, msk, col, lw, lane, 1);
    }
    __syncthreads();
    if (!allvalid) {
        for (int i = tid; i < LNODES * NODE_F; i += 256)
            if (bucket_s[i >> 6] < 0) hB[i] = 0.f;
        __syncthreads();
    }

    // ---- phase 4: readout(h3=hB, W3) split 4/4
    if (w < 4) accA += do_readout(hB, Wt + 3 * WSTEP, 0,  4, redA, sumA, bucket_s, msk, col, lw, lane, 2);
    else       accB += do_readout(hB, Wt + 3 * WSTEP, 32, 4, redB, sumB, bucket_s, msk, col, lw, lane, 1);

    atomicAdd(&d_acc[b * OUT3 + col], (w < 4) ? accA : accB);

    // ---- last-block epilogue: final GEMM + softmax ----
    __threadfence();
    __syncthreads();
    if (tid == 0) {
        int old = atomicAdd(&d_done, 1);
        lastf[0] = (old == (int)(gridDim.x * gridDim.y) - 1);
    }
    __syncthreads();
    if (lastf[0]) {
        __threadfence();
        int bb = tid >> 3;          // 32 rows, 8 threads each
        int o = tid & 7;            // outputs o and o+8
        float s0 = __ldg(bf + o), s1 = __ldg(bf + o + 8);
#pragma unroll 8
        for (int i = 0; i < OUT3; i++) {
            float a = d_acc[bb * OUT3 + i];
            s0 += a * __ldg(Wf + i * TGT + o);
            s1 += a * __ldg(Wf + i * TGT + o + 8);
        }
        float m = fmaxf(s0, s1);
#pragma unroll
        for (int k = 4; k >= 1; k >>= 1) m = fmaxf(m, __shfl_xor_sync(0xffffffffu, m, k));
        float e0 = expf(s0 - m), e1 = expf(s1 - m);
        float sm2 = e0 + e1;
#pragma unroll
        for (int k = 4; k >= 1; k >>= 1) sm2 += __shfl_xor_sync(0xffffffffu, sm2, k);
        out[bb * TGT + o] = e0 / sm2;
        out[bb * TGT + o + 8] = e1 / sm2;
        // reset state for next replay
        __syncthreads();
        for (int i = tid; i < BB * OUT3; i += 256) d_acc[i] = 0.f;
        if (tid == 0) d_done = 0;
    }
}

// ---------------------------------------------------------------------------
extern "C" void kernel_launch(void* const* d_in, const int* in_sizes, int n_in,
                              void* d_out, int out_size) {
    const float* g    = (const float*)d_in[0];
    const float* h_in = (const float*)d_in[1];
    const float* e    = (const float*)d_in[2];
    const float* H0   = (const float*)d_in[3];
    const float* H1   = (const float*)d_in[4];
    const float* H2   = (const float*)d_in[5];
    const float* W0   = (const float*)d_in[6];
    const float* W1   = (const float*)d_in[7];
    const float* W2   = (const float*)d_in[8];
    const float* W3   = (const float*)d_in[9];
    const float* Wf   = (const float*)d_in[10];
    const float* bf   = (const float*)d_in[11];
    float* out = (float*)d_out;

    static int smem_set = 0;
    if (!smem_set) {
        cudaFuncSetAttribute(mega_kernel, cudaFuncAttributeMaxDynamicSharedMemorySize,
                             SMEM_FLOATS * 4);
        smem_set = 1;
    }

    transpose_kernel<<<(HJOBS + WJOBS + 255) / 256, 256>>>(H0, H1, H2, W0, W1, W2, W3);
    mega_kernel<<<dim3(8, BB), 256, SMEM_FLOATS * 4>>>(g, h_in, e, Wf, bf, out);
}

// round 14
// speedup vs baseline: 2.0317x; 1.2336x over previous
#include <cuda_runtime.h>
#include <math.h>

#define BB 32
#define NV 512
#define NODE_F 64
#define EDGE_F 16
#define MSG 80
#define OUT3 128
#define TGT 16

#define CHUNK 64        // output nodes per block
#define HLO 76          // h rows held: CHUNK + 12 halo
#define LNODES 72       // nodes updated per block: CHUNK + 8

// smem layout (floats)
#define OFF_HA    0
#define OFF_HB    (OFF_HA + HLO*NODE_F)          // 4864
#define OFF_ME    (OFF_HB + HLO*NODE_F)          // 9728
#define OFF_G4    (OFF_ME + LNODES*EDGE_F)       // 10880
#define OFF_INT   (OFF_G4 + LNODES*4)            // 11168 (176 ints)
#define OFF_MS    (OFF_INT + 176)                // 11344 (16B aligned)
#define SMEM_FLOATS (OFF_MS + 8*4*MSG)           // 13904 -> 55616 B

#define FMA2(acc, a, b) asm("fma.rn.f32x2 %0, %1, %2, %0;" : "+l"(acc) : "l"(a), "l"(b))
__device__ __forceinline__ float2 unpack2(unsigned long long v) {
    float2 r; asm("mov.b64 {%0,%1}, %2;" : "=f"(r.x), "=f"(r.y) : "l"(v)); return r;
}

// ---------------- device globals ----------------
__device__ float d_acc[BB * OUT3];   // zero at load; re-zeroed by epilogue
__device__ int   d_done = 0;
// quad-major H: u64[ ((step*4+bkt)*20 + i4)*64 + c ][2]
__device__ __align__(16) float d_Ht4[3 * 4 * 20 * NODE_F * 4];
// quad-major W: float4 d_Wq[layer][i4(16)][col(128)] = (W[4i4..4i4+3][col])
__device__ __align__(16) float4 d_Wq[4 * 16 * OUT3];

// ---------------------------------------------------------------------------
// transpose H (quad-major u64 pairs) and W (quad-major float4)
// ---------------------------------------------------------------------------
#define HJOBS (3*4*20*NODE_F*2)      // 30720 float2 jobs
#define WJOBS (4*16*OUT3)            // 8192 float4 jobs
__global__ void transpose_kernel(const float* __restrict__ H0,
                                 const float* __restrict__ H1,
                                 const float* __restrict__ H2,
                                 const float* __restrict__ W0,
                                 const float* __restrict__ W1,
                                 const float* __restrict__ W2,
                                 const float* __restrict__ W3) {
    int idx = blockIdx.x * 256 + threadIdx.x;
    if (idx < HJOBS) {
        int s  = idx / 10240;
        int r  = idx - s * 10240;
        int d  = r / 2560;
        int r2 = r - d * 2560;
        int i4 = r2 / 128;
        int r3 = r2 - i4 * 128;
        int c  = r3 >> 1;
        int half = r3 & 1;
        int row = 4 * i4 + 2 * half;
        const float* H = (s == 0) ? H0 : (s == 1) ? H1 : H2;
        reinterpret_cast<float2*>(d_Ht4)[idx] =
            make_float2(H[(d * MSG + row) * NODE_F + c],
                        H[(d * MSG + row + 1) * NODE_F + c]);
    } else if (idx < HJOBS + WJOBS) {
        int j = idx - HJOBS;
        int layer = j / (16 * OUT3);
        int r = j - layer * (16 * OUT3);
        int i4 = r / OUT3;
        int col = r - i4 * OUT3;
        const float* W = (layer == 0) ? W0 : (layer == 1) ? W1 : (layer == 2) ? W2 : W3;
        d_Wq[j] = make_float4(W[(4 * i4 + 0) * OUT3 + col],
                              W[(4 * i4 + 1) * OUT3 + col],
                              W[(4 * i4 + 2) * OUT3 + col],
                              W[(4 * i4 + 3) * OUT3 + col]);
    }
}

// ---------------------------------------------------------------------------
// one message step, split across 8 warps: hnext[l] = [gather(hprev)|me] @ H[bkt]
// ---------------------------------------------------------------------------
__device__ __forceinline__ void do_step(
    const float* __restrict__ hprev, float* __restrict__ hnext,
    const ulonglong2* __restrict__ Hstep,
    const int* __restrict__ list_s, const int* __restrict__ bucket_s,
    const float* __restrict__ g4f, const float* __restrict__ me_s,
    float* __restrict__ m_s, int G, int w, int lane)
{
    float* mw = m_s + w * (4 * MSG);
    for (int gi = w; gi < G; gi += 8) {
        int l4[4];
#pragma unroll
        for (int j = 0; j < 4; j++) {
            int l = list_s[4 * gi + j];
            l4[j] = l;
            float4 gg = *reinterpret_cast<const float4*>(g4f + l * 4);
            const float* hp = hprev + (l + 1) * NODE_F + 2 * lane;
            float2 h0 = *reinterpret_cast<const float2*>(hp);
            float2 h1 = *reinterpret_cast<const float2*>(hp + NODE_F);
            float2 h2 = *reinterpret_cast<const float2*>(hp + 2 * NODE_F);
            float2 h3 = *reinterpret_cast<const float2*>(hp + 3 * NODE_F);
            float2 m2;
            m2.x = gg.x * h0.x + gg.y * h1.x + gg.z * h2.x + gg.w * h3.x;
            m2.y = gg.x * h0.y + gg.y * h1.y + gg.z * h2.y + gg.w * h3.y;
            *reinterpret_cast<float2*>(mw + j * MSG + 2 * lane) = m2;
            if (lane < 16) mw[j * MSG + 64 + lane] = me_s[l * EDGE_F + lane];
        }
        __syncwarp();
        int bucket = bucket_s[l4[0]];
        const ulonglong2* Hb = Hstep + bucket * (20 * NODE_F);
        unsigned long long a0[4], a1[4];
#pragma unroll
        for (int j = 0; j < 4; j++) { a0[j] = 0ull; a1[j] = 0ull; }
#pragma unroll 4
        for (int i4 = 0; i4 < 20; i4++) {
            ulonglong2 ha  = __ldg(Hb + i4 * NODE_F + lane);
            ulonglong2 hb2 = __ldg(Hb + i4 * NODE_F + lane + 32);
#pragma unroll
            for (int j = 0; j < 4; j++) {
                ulonglong2 mm =
                    *reinterpret_cast<const ulonglong2*>(mw + j * MSG + 4 * i4);
                FMA2(a0[j], mm.x, ha.x);
                FMA2(a0[j], mm.y, ha.y);
                FMA2(a1[j], mm.x, hb2.x);
                FMA2(a1[j], mm.y, hb2.y);
            }
        }
#pragma unroll
        for (int j = 0; j < 4; j++) {
            float2 r0 = unpack2(a0[j]);
            float2 r1 = unpack2(a1[j]);
            float* dst = hnext + l4[j] * NODE_F;
            dst[lane] = r0.x + r0.y;
            dst[lane + 32] = r1.x + r1.y;
        }
        __syncwarp();
    }
}

// ---------------------------------------------------------------------------
// readout v2: ONE warp per 8-node batch; lane owns cols {l, l+32, l+64, l+96}.
// W via LDG.128 (quad-major, L1-resident), h via broadcast LDS.128; feature-
// pair FMA2 with free u64 reinterpret. Softmax reductions fully in-warp.
// ---------------------------------------------------------------------------
__device__ __forceinline__ void do_readout2(
    const float* __restrict__ hbuf, const float4* __restrict__ Wq,
    int nb, const int* __restrict__ bucket_s, int use_mask,
    int lane, float* __restrict__ accCol)
{
    unsigned long long acc[8][4];
#pragma unroll
    for (int j = 0; j < 8; j++)
#pragma unroll
        for (int c = 0; c < 4; c++) acc[j][c] = 0ull;

#pragma unroll
    for (int i4 = 0; i4 < 16; i4++) {
        float4 w0 = __ldg(Wq + i4 * OUT3 + lane);
        float4 w1 = __ldg(Wq + i4 * OUT3 + lane + 32);
        float4 w2 = __ldg(Wq + i4 * OUT3 + lane + 64);
        float4 w3 = __ldg(Wq + i4 * OUT3 + lane + 96);
        ulonglong2 W0 = *reinterpret_cast<ulonglong2*>(&w0);
        ulonglong2 W1 = *reinterpret_cast<ulonglong2*>(&w1);
        ulonglong2 W2 = *reinterpret_cast<ulonglong2*>(&w2);
        ulonglong2 W3 = *reinterpret_cast<ulonglong2*>(&w3);
#pragma unroll
        for (int j = 0; j < 8; j++) {
            float4 h4 = *reinterpret_cast<const float4*>(hbuf + (nb + j) * NODE_F + 4 * i4);
            ulonglong2 hu = *reinterpret_cast<ulonglong2*>(&h4);
            FMA2(acc[j][0], hu.x, W0.x); FMA2(acc[j][0], hu.y, W0.y);
            FMA2(acc[j][1], hu.x, W1.x); FMA2(acc[j][1], hu.y, W1.y);
            FMA2(acc[j][2], hu.x, W2.x); FMA2(acc[j][2], hu.y, W2.y);
            FMA2(acc[j][3], hu.x, W3.x); FMA2(acc[j][3], hu.y, W3.y);
        }
    }

#pragma unroll
    for (int j = 0; j < 8; j++) {
        float2 p0 = unpack2(acc[j][0]);
        float2 p1 = unpack2(acc[j][1]);
        float2 p2 = unpack2(acc[j][2]);
        float2 p3 = unpack2(acc[j][3]);
        float lin0 = p0.x + p0.y, lin1 = p1.x + p1.y;
        float lin2 = p2.x + p2.y, lin3 = p3.x + p3.y;
        float m = fmaxf(fmaxf(lin0, lin1), fmaxf(lin2, lin3));
#pragma unroll
        for (int k = 16; k >= 1; k >>= 1) m = fmaxf(m, __shfl_xor_sync(0xffffffffu, m, k));
        float e0 = __expf(lin0 - m), e1 = __expf(lin1 - m);
        float e2 = __expf(lin2 - m), e3 = __expf(lin3 - m);
        float s = (e0 + e1) + (e2 + e3);
#pragma unroll
        for (int k = 16; k >= 1; k >>= 1) s += __shfl_xor_sync(0xffffffffu, s, k);
        int keep = use_mask ? (bucket_s[nb + j] >= 0) : 1;
        if (keep) {
            float inv = __fdividef(1.f, s);
            accCol[0] += e0 * inv; accCol[1] += e1 * inv;
            accCol[2] += e2 * inv; accCol[3] += e3 * inv;
        }
    }
}

// ---------------------------------------------------------------------------
// mega kernel: one 64-node chunk per block. Prologue (all threads), then 4
// phases: P1 step0+readout L0, P2 step1+L1, P3 step2+L2, P4 L3. All 8 warps
// share both step (gi+=8) and readout (1 batch/warp). Last block = epilogue.
// ---------------------------------------------------------------------------
__global__ void __launch_bounds__(256, 2) mega_kernel(
    const float* __restrict__ g, const float* __restrict__ h_in,
    const float* __restrict__ e,
    const float* __restrict__ Wf, const float* __restrict__ bf,
    float* __restrict__ out)
{
    extern __shared__ float sm[];
    float* hA   = sm + OFF_HA;
    float* hB   = sm + OFF_HB;
    float* me_s = sm + OFF_ME;
    float* g4f  = sm + OFF_G4;
    int*   ip   = (int*)(sm + OFF_INT);
    int* bucket_s = ip;            // 72
    int* list_s   = ip + 72;       // 88
    int* bcnt     = ip + 160;      // 4
    int* boff     = ip + 164;      // 4
    int* pcnt     = ip + 168;      // 4
    int* gtot     = ip + 172;
    int* vflag    = ip + 173;
    int* lastf    = ip + 174;
    float* m_s  = sm + OFF_MS;

    int tid = threadIdx.x;
    int b = blockIdx.y;
    int s = blockIdx.x * CHUNK;
    int w = tid >> 5, lane = tid & 31;

    if (tid < 4) { bcnt[tid] = 0; pcnt[tid] = 0; }

    // ---- prologue (all 256 threads) ----
    for (int i = tid; i < HLO * 16; i += 256) {
        int row = i >> 4, q = i & 15;
        int v = (s + row) & (NV - 1);
        reinterpret_cast<float4*>(hA)[i] =
            __ldg(reinterpret_cast<const float4*>(h_in + ((size_t)(b * NV + v) << 6)) + q);
    }
    if (tid < LNODES) {
        int v = (s + tid) & (NV - 1);
        const float* grow = g + (size_t)(b * NV + v) * NV;
        float g0 = __ldg(grow + ((v + 1) & (NV - 1)));
        float g1 = __ldg(grow + ((v + 2) & (NV - 1)));
        float g2 = __ldg(grow + ((v + 3) & (NV - 1)));
        float g3 = __ldg(grow + ((v + 4) & (NV - 1)));
        g4f[tid * 4 + 0] = g0; g4f[tid * 4 + 1] = g1;
        g4f[tid * 4 + 2] = g2; g4f[tid * 4 + 3] = g3;
        float deg = g0 + g1 + g2 + g3;
        int d = (int)(deg + 0.5f) - 1;
        bool valid = (d >= 0) && (d < 4) && (fabsf(deg - (float)(d + 1)) < 1e-4f);
        if (valid) { atomicAdd(&bcnt[d], 1); bucket_s[tid] = d; }
        else bucket_s[tid] = -1;
    }
    __syncthreads();
    if (tid == 0) {
        int off = 0, gt = 0, tot = 0;
        for (int d = 0; d < 4; d++) {
            boff[d] = off;
            int pc = (bcnt[d] + 3) & ~3;
            off += pc; gt += pc >> 2; tot += bcnt[d];
        }
        gtot[0] = gt;
        vflag[0] = (tot == LNODES);
    }
    __syncthreads();
    if (tid < LNODES && bucket_s[tid] >= 0) {
        int d = bucket_s[tid];
        int pos = atomicAdd(&pcnt[d], 1);
        list_s[boff[d] + pos] = tid;
    }
    for (int i = tid; i < LNODES * EDGE_F; i += 256) {
        int l = i >> 4, c = i & 15;
        int v = (s + l) & (NV - 1);
        const float* eb = e + ((size_t)(b * NV + v) * NV) * EDGE_F;
        me_s[i] = g4f[l * 4 + 0] * __ldg(eb + ((v + 1) & (NV - 1)) * EDGE_F + c)
                + g4f[l * 4 + 1] * __ldg(eb + ((v + 2) & (NV - 1)) * EDGE_F + c)
                + g4f[l * 4 + 2] * __ldg(eb + ((v + 3) & (NV - 1)) * EDGE_F + c)
                + g4f[l * 4 + 3] * __ldg(eb + ((v + 4) & (NV - 1)) * EDGE_F + c);
    }
    __syncthreads();
    if (tid < 4) {   // pad bucket lists to multiple of 4
        int c = bcnt[tid];
        if (c > 0) {
            int pc = (c + 3) & ~3;
            int last = list_s[boff[tid] + c - 1];
            for (int p = c; p < pc; p++) list_s[boff[tid] + p] = last;
        }
    }
    __syncthreads();
    int G = gtot[0];
    int allvalid = vflag[0];
    int msk = !allvalid;

    const ulonglong2* Ht4 = reinterpret_cast<const ulonglong2*>(d_Ht4);
    const int HSTEP = 4 * 20 * NODE_F;   // ulonglong2 per step
    int nb = w * 8;                      // this warp's batch (node base)
    float accCol[4] = {0.f, 0.f, 0.f, 0.f};

    // ---- P1: step0 (hA->hB) + readout L0 (hA) ----
    do_readout2(hA, d_Wq + 0 * 16 * OUT3, nb, bucket_s, 0, lane, accCol);
    do_step(hA, hB, Ht4, list_s, bucket_s, g4f, me_s, m_s, G, w, lane);
    __syncthreads();
    if (!allvalid) {
        for (int i = tid; i < LNODES * NODE_F; i += 256)
            if (bucket_s[i >> 6] < 0) hB[i] = 0.f;
        __syncthreads();
    }

    // ---- P2: step1 (hB->hA) + readout L1 (hB) ----
    do_readout2(hB, d_Wq + 1 * 16 * OUT3, nb, bucket_s, msk, lane, accCol);
    do_step(hB, hA, Ht4 + HSTEP, list_s, bucket_s, g4f, me_s, m_s, G, w, lane);
    __syncthreads();
    if (!allvalid) {
        for (int i = tid; i < LNODES * NODE_F; i += 256)
            if (bucket_s[i >> 6] < 0) hA[i] = 0.f;
        __syncthreads();
    }

    // ---- P3: step2 (hA->hB) + readout L2 (hA) ----
    do_readout2(hA, d_Wq + 2 * 16 * OUT3, nb, bucket_s, msk, lane, accCol);
    do_step(hA, hB, Ht4 + 2 * HSTEP, list_s, bucket_s, g4f, me_s, m_s, G, w, lane);
    __syncthreads();
    if (!allvalid) {
        for (int i = tid; i < LNODES * NODE_F; i += 256)
            if (bucket_s[i >> 6] < 0) hB[i] = 0.f;
        __syncthreads();
    }

    // ---- P4: readout L3 (hB) ----
    do_readout2(hB, d_Wq + 3 * 16 * OUT3, nb, bucket_s, msk, lane, accCol);

    atomicAdd(&d_acc[b * OUT3 + lane],      accCol[0]);
    atomicAdd(&d_acc[b * OUT3 + lane + 32], accCol[1]);
    atomicAdd(&d_acc[b * OUT3 + lane + 64], accCol[2]);
    atomicAdd(&d_acc[b * OUT3 + lane + 96], accCol[3]);

    // ---- last-block epilogue: final GEMM + softmax ----
    __threadfence();
    __syncthreads();
    if (tid == 0) {
        int old = atomicAdd(&d_done, 1);
        lastf[0] = (old == (int)(gridDim.x * gridDim.y) - 1);
    }
    __syncthreads();
    if (lastf[0]) {
        __threadfence();
        int bb = tid >> 3;          // 32 rows, 8 threads each
        int o = tid & 7;            // outputs o and o+8
        float s0 = __ldg(bf + o), s1 = __ldg(bf + o + 8);
#pragma unroll 8
        for (int i = 0; i < OUT3; i++) {
            float a = d_acc[bb * OUT3 + i];
            s0 += a * __ldg(Wf + i * TGT + o);
            s1 += a * __ldg(Wf + i * TGT + o + 8);
        }
        float m = fmaxf(s0, s1);
#pragma unroll
        for (int k = 4; k >= 1; k >>= 1) m = fmaxf(m, __shfl_xor_sync(0xffffffffu, m, k));
        float e0 = expf(s0 - m), e1 = expf(s1 - m);
        float sm2 = e0 + e1;
#pragma unroll
        for (int k = 4; k >= 1; k >>= 1) sm2 += __shfl_xor_sync(0xffffffffu, sm2, k);
        out[bb * TGT + o] = e0 / sm2;
        out[bb * TGT + o + 8] = e1 / sm2;
        // reset state for next replay
        __syncthreads();
        for (int i = tid; i < BB * OUT3; i += 256) d_acc[i] = 0.f;
        if (tid == 0) d_done = 0;
    }
}

// ---------------------------------------------------------------------------
extern "C" void kernel_launch(void* const* d_in, const int* in_sizes, int n_in,
                              void* d_out, int out_size) {
    const float* g    = (const float*)d_in[0];
    const float* h_in = (const float*)d_in[1];
    const float* e    = (const float*)d_in[2];
    const float* H0   = (const float*)d_in[3];
    const float* H1   = (const float*)d_in[4];
    const float* H2   = (const float*)d_in[5];
    const float* W0   = (const float*)d_in[6];
    const float* W1   = (const float*)d_in[7];
    const float* W2   = (const float*)d_in[8];
    const float* W3   = (const float*)d_in[9];
    const float* Wf   = (const float*)d_in[10];
    const float* bf   = (const float*)d_in[11];
    float* out = (float*)d_out;

    static int smem_set = 0;
    if (!smem_set) {
        cudaFuncSetAttribute(mega_kernel, cudaFuncAttributeMaxDynamicSharedMemorySize,
                             SMEM_FLOATS * 4);
        smem_set = 1;
    }

    transpose_kernel<<<(HJOBS + WJOBS + 255) / 256, 256>>>(H0, H1, H2, W0, W1, W2, W3);
    mega_kernel<<<dim3(8, BB), 256, SMEM_FLOATS * 4>>>(g, h_in, e, Wf, bf, out);
}

// round 15
// speedup vs baseline: 2.1206x; 1.0438x over previous
#include <cuda_runtime.h>
#include <math.h>

#define BB 32
#define NV 512
#define NODE_F 64
#define EDGE_F 16
#define MSG 80
#define OUT3 128
#define TGT 16

#define CHUNK 64        // output nodes per block
#define HLO 76          // h rows held: CHUNK + 12 halo
#define LNODES 72       // nodes updated per block: CHUNK + 8

// smem layout (floats)
#define OFF_HA    0
#define OFF_HB    (OFF_HA + HLO*NODE_F)          // 4864
#define OFF_ME    (OFF_HB + HLO*NODE_F)          // 9728
#define OFF_G4    (OFF_ME + LNODES*EDGE_F)       // 10880
#define OFF_INT   (OFF_G4 + LNODES*4)            // 11168 (176 ints)
#define OFF_MS    (OFF_INT + 176)                // 11344 (16B aligned)
#define SMEM_FLOATS (OFF_MS + 8*4*MSG)           // 13904 -> 55616 B

#define FMA2(acc, a, b) asm("fma.rn.f32x2 %0, %1, %2, %0;" : "+l"(acc) : "l"(a), "l"(b))
__device__ __forceinline__ float2 unpack2(unsigned long long v) {
    float2 r; asm("mov.b64 {%0,%1}, %2;" : "=f"(r.x), "=f"(r.y) : "l"(v)); return r;
}

// ---------------- device globals ----------------
__device__ float d_acc[BB * OUT3];   // zero at load; re-zeroed by epilogue
__device__ int   d_done = 0;
// quad-major H: u64[ ((step*4+bkt)*20 + i4)*64 + c ][2]
__device__ __align__(16) float d_Ht4[3 * 4 * 20 * NODE_F * 4];
// quad-major W: float4 d_Wq[layer][i4(16)][col(128)] = (W[4i4..4i4+3][col])
__device__ __align__(16) float4 d_Wq[4 * 16 * OUT3];

// ---------------------------------------------------------------------------
// transpose H (quad-major u64 pairs) and W (quad-major float4)
// ---------------------------------------------------------------------------
#define HJOBS (3*4*20*NODE_F*2)      // 30720 float2 jobs
#define WJOBS (4*16*OUT3)            // 8192 float4 jobs
__global__ void transpose_kernel(const float* __restrict__ H0,
                                 const float* __restrict__ H1,
                                 const float* __restrict__ H2,
                                 const float* __restrict__ W0,
                                 const float* __restrict__ W1,
                                 const float* __restrict__ W2,
                                 const float* __restrict__ W3) {
    int idx = blockIdx.x * 256 + threadIdx.x;
    if (idx < HJOBS) {
        int s  = idx / 10240;
        int r  = idx - s * 10240;
        int d  = r / 2560;
        int r2 = r - d * 2560;
        int i4 = r2 / 128;
        int r3 = r2 - i4 * 128;
        int c  = r3 >> 1;
        int half = r3 & 1;
        int row = 4 * i4 + 2 * half;
        const float* H = (s == 0) ? H0 : (s == 1) ? H1 : H2;
        reinterpret_cast<float2*>(d_Ht4)[idx] =
            make_float2(H[(d * MSG + row) * NODE_F + c],
                        H[(d * MSG + row + 1) * NODE_F + c]);
    } else if (idx < HJOBS + WJOBS) {
        int j = idx - HJOBS;
        int layer = j / (16 * OUT3);
        int r = j - layer * (16 * OUT3);
        int i4 = r / OUT3;
        int col = r - i4 * OUT3;
        const float* W = (layer == 0) ? W0 : (layer == 1) ? W1 : (layer == 2) ? W2 : W3;
        d_Wq[j] = make_float4(W[(4 * i4 + 0) * OUT3 + col],
                              W[(4 * i4 + 1) * OUT3 + col],
                              W[(4 * i4 + 2) * OUT3 + col],
                              W[(4 * i4 + 3) * OUT3 + col]);
    }
}

// ---------------------------------------------------------------------------
// one message step, split across 8 warps: hnext[l] = [gather(hprev)|me] @ H[bkt]
// ---------------------------------------------------------------------------
__device__ __forceinline__ void do_step(
    const float* __restrict__ hprev, float* __restrict__ hnext,
    const ulonglong2* __restrict__ Hstep,
    const int* __restrict__ list_s, const int* __restrict__ bucket_s,
    const float* __restrict__ g4f, const float* __restrict__ me_s,
    float* __restrict__ m_s, int G, int w, int lane)
{
    float* mw = m_s + w * (4 * MSG);
    for (int gi = w; gi < G; gi += 8) {
        int l4[4];
#pragma unroll
        for (int j = 0; j < 4; j++) {
            int l = list_s[4 * gi + j];
            l4[j] = l;
            float4 gg = *reinterpret_cast<const float4*>(g4f + l * 4);
            const float* hp = hprev + (l + 1) * NODE_F + 2 * lane;
            float2 h0 = *reinterpret_cast<const float2*>(hp);
            float2 h1 = *reinterpret_cast<const float2*>(hp + NODE_F);
            float2 h2 = *reinterpret_cast<const float2*>(hp + 2 * NODE_F);
            float2 h3 = *reinterpret_cast<const float2*>(hp + 3 * NODE_F);
            float2 m2;
            m2.x = gg.x * h0.x + gg.y * h1.x + gg.z * h2.x + gg.w * h3.x;
            m2.y = gg.x * h0.y + gg.y * h1.y + gg.z * h2.y + gg.w * h3.y;
            *reinterpret_cast<float2*>(mw + j * MSG + 2 * lane) = m2;
            if (lane < 16) mw[j * MSG + 64 + lane] = me_s[l * EDGE_F + lane];
        }
        __syncwarp();
        int bucket = bucket_s[l4[0]];
        const ulonglong2* Hb = Hstep + bucket * (20 * NODE_F);
        unsigned long long a0[4], a1[4];
#pragma unroll
        for (int j = 0; j < 4; j++) { a0[j] = 0ull; a1[j] = 0ull; }
#pragma unroll 4
        for (int i4 = 0; i4 < 20; i4++) {
            ulonglong2 ha  = __ldg(Hb + i4 * NODE_F + lane);
            ulonglong2 hb2 = __ldg(Hb + i4 * NODE_F + lane + 32);
#pragma unroll
            for (int j = 0; j < 4; j++) {
                ulonglong2 mm =
                    *reinterpret_cast<const ulonglong2*>(mw + j * MSG + 4 * i4);
                FMA2(a0[j], mm.x, ha.x);
                FMA2(a0[j], mm.y, ha.y);
                FMA2(a1[j], mm.x, hb2.x);
                FMA2(a1[j], mm.y, hb2.y);
            }
        }
#pragma unroll
        for (int j = 0; j < 4; j++) {
            float2 r0 = unpack2(a0[j]);
            float2 r1 = unpack2(a1[j]);
            float* dst = hnext + l4[j] * NODE_F;
            dst[lane] = r0.x + r0.y;
            dst[lane + 32] = r1.x + r1.y;
        }
        __syncwarp();
    }
}

// ---------------------------------------------------------------------------
// readout v2: ONE warp per 8-node batch; lane owns cols {l, l+32, l+64, l+96}.
// W via LDG.128 (quad-major, L1-resident), h via broadcast LDS.128.
// Softmax epilogue: nodes processed in groups of 4 with butterfly loops
// hoisted outside the node loop -> 4 independent SHFL chains per round.
// ---------------------------------------------------------------------------
__device__ __forceinline__ void do_readout2(
    const float* __restrict__ hbuf, const float4* __restrict__ Wq,
    int nb, const int* __restrict__ bucket_s, int use_mask,
    int lane, float* __restrict__ accCol)
{
    unsigned long long acc[8][4];
#pragma unroll
    for (int j = 0; j < 8; j++)
#pragma unroll
        for (int c = 0; c < 4; c++) acc[j][c] = 0ull;

#pragma unroll
    for (int i4 = 0; i4 < 16; i4++) {
        float4 w0 = __ldg(Wq + i4 * OUT3 + lane);
        float4 w1 = __ldg(Wq + i4 * OUT3 + lane + 32);
        float4 w2 = __ldg(Wq + i4 * OUT3 + lane + 64);
        float4 w3 = __ldg(Wq + i4 * OUT3 + lane + 96);
        ulonglong2 W0 = *reinterpret_cast<ulonglong2*>(&w0);
        ulonglong2 W1 = *reinterpret_cast<ulonglong2*>(&w1);
        ulonglong2 W2 = *reinterpret_cast<ulonglong2*>(&w2);
        ulonglong2 W3 = *reinterpret_cast<ulonglong2*>(&w3);
#pragma unroll
        for (int j = 0; j < 8; j++) {
            float4 h4 = *reinterpret_cast<const float4*>(hbuf + (nb + j) * NODE_F + 4 * i4);
            ulonglong2 hu = *reinterpret_cast<ulonglong2*>(&h4);
            FMA2(acc[j][0], hu.x, W0.x); FMA2(acc[j][0], hu.y, W0.y);
            FMA2(acc[j][1], hu.x, W1.x); FMA2(acc[j][1], hu.y, W1.y);
            FMA2(acc[j][2], hu.x, W2.x); FMA2(acc[j][2], hu.y, W2.y);
            FMA2(acc[j][3], hu.x, W3.x); FMA2(acc[j][3], hu.y, W3.y);
        }
    }

    // epilogue: two groups of 4 nodes; reductions interleaved across nodes
#pragma unroll
    for (int half = 0; half < 2; half++) {
        float l0[4], l1[4], l2[4], l3[4], mx[4], ss[4];
#pragma unroll
        for (int q = 0; q < 4; q++) {
            int j = half * 4 + q;
            float2 p0 = unpack2(acc[j][0]);
            float2 p1 = unpack2(acc[j][1]);
            float2 p2 = unpack2(acc[j][2]);
            float2 p3 = unpack2(acc[j][3]);
            l0[q] = p0.x + p0.y; l1[q] = p1.x + p1.y;
            l2[q] = p2.x + p2.y; l3[q] = p3.x + p3.y;
            mx[q] = fmaxf(fmaxf(l0[q], l1[q]), fmaxf(l2[q], l3[q]));
        }
#pragma unroll
        for (int k = 16; k >= 1; k >>= 1) {
#pragma unroll
            for (int q = 0; q < 4; q++)
                mx[q] = fmaxf(mx[q], __shfl_xor_sync(0xffffffffu, mx[q], k));
        }
#pragma unroll
        for (int q = 0; q < 4; q++) {
            l0[q] = __expf(l0[q] - mx[q]); l1[q] = __expf(l1[q] - mx[q]);
            l2[q] = __expf(l2[q] - mx[q]); l3[q] = __expf(l3[q] - mx[q]);
            ss[q] = (l0[q] + l1[q]) + (l2[q] + l3[q]);
        }
#pragma unroll
        for (int k = 16; k >= 1; k >>= 1) {
#pragma unroll
            for (int q = 0; q < 4; q++)
                ss[q] += __shfl_xor_sync(0xffffffffu, ss[q], k);
        }
#pragma unroll
        for (int q = 0; q < 4; q++) {
            int j = half * 4 + q;
            int keep = use_mask ? (bucket_s[nb + j] >= 0) : 1;
            if (keep) {
                float inv = __fdividef(1.f, ss[q]);
                accCol[0] += l0[q] * inv; accCol[1] += l1[q] * inv;
                accCol[2] += l2[q] * inv; accCol[3] += l3[q] * inv;
            }
        }
    }
}

// ---------------------------------------------------------------------------
// mega kernel: one 64-node chunk per block. Prologue (all threads), then 4
// phases: P1 step0+readout L0, P2 step1+L1, P3 step2+L2, P4 L3. All 8 warps
// share both step (gi+=8) and readout (1 batch/warp). Last block = epilogue.
// ---------------------------------------------------------------------------
__global__ void __launch_bounds__(256, 2) mega_kernel(
    const float* __restrict__ g, const float* __restrict__ h_in,
    const float* __restrict__ e,
    const float* __restrict__ Wf, const float* __restrict__ bf,
    float* __restrict__ out)
{
    extern __shared__ float sm[];
    float* hA   = sm + OFF_HA;
    float* hB   = sm + OFF_HB;
    float* me_s = sm + OFF_ME;
    float* g4f  = sm + OFF_G4;
    int*   ip   = (int*)(sm + OFF_INT);
    int* bucket_s = ip;            // 72
    int* list_s   = ip + 72;       // 88
    int* bcnt     = ip + 160;      // 4
    int* boff     = ip + 164;      // 4
    int* pcnt     = ip + 168;      // 4
    int* gtot     = ip + 172;
    int* vflag    = ip + 173;
    int* lastf    = ip + 174;
    float* m_s  = sm + OFF_MS;

    int tid = threadIdx.x;
    int b = blockIdx.y;
    int s = blockIdx.x * CHUNK;
    int w = tid >> 5, lane = tid & 31;

    if (tid < 4) { bcnt[tid] = 0; pcnt[tid] = 0; }

    // ---- prologue (all 256 threads) ----
    for (int i = tid; i < HLO * 16; i += 256) {
        int row = i >> 4, q = i & 15;
        int v = (s + row) & (NV - 1);
        reinterpret_cast<float4*>(hA)[i] =
            __ldg(reinterpret_cast<const float4*>(h_in + ((size_t)(b * NV + v) << 6)) + q);
    }
    if (tid < LNODES) {
        int v = (s + tid) & (NV - 1);
        const float* grow = g + (size_t)(b * NV + v) * NV;
        float g0 = __ldg(grow + ((v + 1) & (NV - 1)));
        float g1 = __ldg(grow + ((v + 2) & (NV - 1)));
        float g2 = __ldg(grow + ((v + 3) & (NV - 1)));
        float g3 = __ldg(grow + ((v + 4) & (NV - 1)));
        g4f[tid * 4 + 0] = g0; g4f[tid * 4 + 1] = g1;
        g4f[tid * 4 + 2] = g2; g4f[tid * 4 + 3] = g3;
        float deg = g0 + g1 + g2 + g3;
        int d = (int)(deg + 0.5f) - 1;
        bool valid = (d >= 0) && (d < 4) && (fabsf(deg - (float)(d + 1)) < 1e-4f);
        if (valid) { atomicAdd(&bcnt[d], 1); bucket_s[tid] = d; }
        else bucket_s[tid] = -1;
    }
    __syncthreads();
    if (tid == 0) {
        int off = 0, gt = 0, tot = 0;
        for (int d = 0; d < 4; d++) {
            boff[d] = off;
            int pc = (bcnt[d] + 3) & ~3;
            off += pc; gt += pc >> 2; tot += bcnt[d];
        }
        gtot[0] = gt;
        vflag[0] = (tot == LNODES);
    }
    __syncthreads();
    if (tid < LNODES && bucket_s[tid] >= 0) {
        int d = bucket_s[tid];
        int pos = atomicAdd(&pcnt[d], 1);
        list_s[boff[d] + pos] = tid;
    }
    for (int i = tid; i < LNODES * EDGE_F; i += 256) {
        int l = i >> 4, c = i & 15;
        int v = (s + l) & (NV - 1);
        const float* eb = e + ((size_t)(b * NV + v) * NV) * EDGE_F;
        me_s[i] = g4f[l * 4 + 0] * __ldg(eb + ((v + 1) & (NV - 1)) * EDGE_F + c)
                + g4f[l * 4 + 1] * __ldg(eb + ((v + 2) & (NV - 1)) * EDGE_F + c)
                + g4f[l * 4 + 2] * __ldg(eb + ((v + 3) & (NV - 1)) * EDGE_F + c)
                + g4f[l * 4 + 3] * __ldg(eb + ((v + 4) & (NV - 1)) * EDGE_F + c);
    }
    __syncthreads();
    if (tid < 4) {   // pad bucket lists to multiple of 4
        int c = bcnt[tid];
        if (c > 0) {
            int pc = (c + 3) & ~3;
            int last = list_s[boff[tid] + c - 1];
            for (int p = c; p < pc; p++) list_s[boff[tid] + p] = last;
        }
    }
    __syncthreads();
    int G = gtot[0];
    int allvalid = vflag[0];
    int msk = !allvalid;

    const ulonglong2* Ht4 = reinterpret_cast<const ulonglong2*>(d_Ht4);
    const int HSTEP = 4 * 20 * NODE_F;   // ulonglong2 per step
    int nb = w * 8;                      // this warp's batch (node base)
    float accCol[4] = {0.f, 0.f, 0.f, 0.f};

    // ---- P1: step0 (hA->hB) + readout L0 (hA) ----
    do_readout2(hA, d_Wq + 0 * 16 * OUT3, nb, bucket_s, 0, lane, accCol);
    do_step(hA, hB, Ht4, list_s, bucket_s, g4f, me_s, m_s, G, w, lane);
    __syncthreads();
    if (!allvalid) {
        for (int i = tid; i < LNODES * NODE_F; i += 256)
            if (bucket_s[i >> 6] < 0) hB[i] = 0.f;
        __syncthreads();
    }

    // ---- P2: step1 (hB->hA) + readout L1 (hB) ----
    do_readout2(hB, d_Wq + 1 * 16 * OUT3, nb, bucket_s, msk, lane, accCol);
    do_step(hB, hA, Ht4 + HSTEP, list_s, bucket_s, g4f, me_s, m_s, G, w, lane);
    __syncthreads();
    if (!allvalid) {
        for (int i = tid; i < LNODES * NODE_F; i += 256)
            if (bucket_s[i >> 6] < 0) hA[i] = 0.f;
        __syncthreads();
    }

    // ---- P3: step2 (hA->hB) + readout L2 (hA) ----
    do_readout2(hA, d_Wq + 2 * 16 * OUT3, nb, bucket_s, msk, lane, accCol);
    do_step(hA, hB, Ht4 + 2 * HSTEP, list_s, bucket_s, g4f, me_s, m_s, G, w, lane);
    __syncthreads();
    if (!allvalid) {
        for (int i = tid; i < LNODES * NODE_F; i += 256)
            if (bucket_s[i >> 6] < 0) hB[i] = 0.f;
        __syncthreads();
    }

    // ---- P4: readout L3 (hB) ----
    do_readout2(hB, d_Wq + 3 * 16 * OUT3, nb, bucket_s, msk, lane, accCol);

    atomicAdd(&d_acc[b * OUT3 + lane],      accCol[0]);
    atomicAdd(&d_acc[b * OUT3 + lane + 32], accCol[1]);
    atomicAdd(&d_acc[b * OUT3 + lane + 64], accCol[2]);
    atomicAdd(&d_acc[b * OUT3 + lane + 96], accCol[3]);

    // ---- last-block epilogue: final GEMM + softmax ----
    __threadfence();
    __syncthreads();
    if (tid == 0) {
        int old = atomicAdd(&d_done, 1);
        lastf[0] = (old == (int)(gridDim.x * gridDim.y) - 1);
    }
    __syncthreads();
    if (lastf[0]) {
        __threadfence();
        int bb = tid >> 3;          // 32 rows, 8 threads each
        int o = tid & 7;            // outputs o and o+8
        float s0 = __ldg(bf + o), s1 = __ldg(bf + o + 8);
#pragma unroll 8
        for (int i = 0; i < OUT3; i++) {
            float a = d_acc[bb * OUT3 + i];
            s0 += a * __ldg(Wf + i * TGT + o);
            s1 += a * __ldg(Wf + i * TGT + o + 8);
        }
        float m = fmaxf(s0, s1);
#pragma unroll
        for (int k = 4; k >= 1; k >>= 1) m = fmaxf(m, __shfl_xor_sync(0xffffffffu, m, k));
        float e0 = expf(s0 - m), e1 = expf(s1 - m);
        float sm2 = e0 + e1;
#pragma unroll
        for (int k = 4; k >= 1; k >>= 1) sm2 += __shfl_xor_sync(0xffffffffu, sm2, k);
        out[bb * TGT + o] = e0 / sm2;
        out[bb * TGT + o + 8] = e1 / sm2;
        // reset state for next replay
        __syncthreads();
        for (int i = tid; i < BB * OUT3; i += 256) d_acc[i] = 0.f;
        if (tid == 0) d_done = 0;
    }
}

// ---------------------------------------------------------------------------
extern "C" void kernel_launch(void* const* d_in, const int* in_sizes, int n_in,
                              void* d_out, int out_size) {
    const float* g    = (const float*)d_in[0];
    const float* h_in = (const float*)d_in[1];
    const float* e    = (const float*)d_in[2];
    const float* H0   = (const float*)d_in[3];
    const float* H1   = (const float*)d_in[4];
    const float* H2   = (const float*)d_in[5];
    const float* W0   = (const float*)d_in[6];
    const float* W1   = (const float*)d_in[7];
    const float* W2   = (const float*)d_in[8];
    const float* W3   = (const float*)d_in[9];
    const float* Wf   = (const float*)d_in[10];
    const float* bf   = (const float*)d_in[11];
    float* out = (float*)d_out;

    static int smem_set = 0;
    if (!smem_set) {
        cudaFuncSetAttribute(mega_kernel, cudaFuncAttributeMaxDynamicSharedMemorySize,
                             SMEM_FLOATS * 4);
        smem_set = 1;
    }

    transpose_kernel<<<(HJOBS + WJOBS + 255) / 256, 256>>>(H0, H1, H2, W0, W1, W2, W3);
    mega_kernel<<<dim3(8, BB), 256, SMEM_FLOATS * 4>>>(g, h_in, e, Wf, bf, out);
}